// round 12
// baseline (speedup 1.0000x reference)
#include <cuda_runtime.h>
#include <cuda_fp16.h>

#define NU 100000
#define MI 50000
#define NN (NU + MI)
#define D 64
#define ND (NN * D)
#define ND4 (ND / 4)
#define MAXE 2000000
#define CHUNK 2048
#define NBLK_I ((MI + CHUNK - 1) / CHUNK)   // 25

// Static scratch (no dynamic allocation allowed).
static __device__ __half g_h0[ND];                    // fp16 copy of concat(eu0, ei0)
static __device__ __half g_a[ND];                     // layer 1 out (fp16)
static __device__ __half g_b[ND];                     // layer 2 out (fp16)
static __device__ unsigned long long g_edges[MAXE];   // ITEM half only: {val:f32, col:u32}
static __device__ int g_rowptr[NU + 1];               // user CSR into cols/vals arrays
static __device__ int g_rowptr_i[MI + 1];             // item CSR into g_edges (0-based)
static __device__ int g_cursor[MI];                   // zero at entry; rebuilt+rezeroed
static __device__ int g_flag[NBLK_I];                 // scan decoupling flags (zero at entry)

// ---------------------------------------------------------------------------
struct StreamRes {
    cudaStream_t side = nullptr;
    cudaEvent_t eFork = nullptr, eHist = nullptr, eConv = nullptr,
                eScat = nullptr, eL1u = nullptr, eSide = nullptr;
    bool ok = false;
    StreamRes() {
        if (cudaStreamCreateWithFlags(&side, cudaStreamNonBlocking) != cudaSuccess) return;
        if (cudaEventCreateWithFlags(&eFork, cudaEventDisableTiming) != cudaSuccess) return;
        if (cudaEventCreateWithFlags(&eHist, cudaEventDisableTiming) != cudaSuccess) return;
        if (cudaEventCreateWithFlags(&eConv, cudaEventDisableTiming) != cudaSuccess) return;
        if (cudaEventCreateWithFlags(&eScat, cudaEventDisableTiming) != cudaSuccess) return;
        if (cudaEventCreateWithFlags(&eL1u, cudaEventDisableTiming) != cudaSuccess) return;
        if (cudaEventCreateWithFlags(&eSide, cudaEventDisableTiming) != cudaSuccess) return;
        ok = true;
    }
};
static StreamRes g_sr;

// ---------------------------------------------------------------------------
// convert inputs to fp16 table; out[2B] = 0
__global__ void convert_init_kernel(const float4* __restrict__ eu,
                                    const float4* __restrict__ ei,
                                    float* __restrict__ out, int B) {
    int i = blockIdx.x * blockDim.x + threadIdx.x;
    if (i < ND4) {
        const int NU4 = NU * D / 4;
        float4 v = (i < NU4) ? __ldg(eu + i) : __ldg(ei + (i - NU4));
        half2 h[2];
        h[0] = __floats2half2_rn(v.x, v.y);
        h[1] = __floats2half2_rn(v.z, v.w);
        ((uint2*)g_h0)[i] = *(uint2*)h;
    }
    if (i == 0) out[2 * B] = 0.f;
}

// re-zero cursors + scan flags (tail of launch; entry state is always zero)
__global__ void clear_kernel() {
    int i = blockIdx.x * blockDim.x + threadIdx.x;
    if (i < MI) g_cursor[i] = 0;
    if (i < NBLK_I) g_flag[i] = 0;
}

// user rowptr boundary detection (first half, sorted) + item-degree histogram.
// NO edge copy — user CSR edges ARE cols/vals[0..H).
__global__ void hist_kernel(const int* __restrict__ rows, int H) {
    int e = blockIdx.x * blockDim.x + threadIdx.x;
    if (e >= H) return;
    int cur = __ldg(&rows[e]);
    int prev = (e == 0) ? -1 : __ldg(&rows[e - 1]);
    for (int r = prev + 1; r <= cur; r++) g_rowptr[r] = e;
    if (e == H - 1)
        for (int r = cur + 1; r <= NU; r++) g_rowptr[r] = H;
    atomicAdd(&g_cursor[__ldg(&rows[H + e]) - NU], 1);
}

// single-kernel decoupled scan of item degrees -> g_rowptr_i (0-based) + cursors.
// 25 blocks (all co-resident); block b publishes total+1, spins on predecessors.
__global__ void scan_fused_kernel(int H) {
    __shared__ int ssum[256];
    __shared__ int s_off;
    int b = blockIdx.x, t = threadIdx.x;
    int base = b * CHUNK + t * 8;
    int v[8];
    int s = 0;
#pragma unroll
    for (int k = 0; k < 8; k++) {
        int idx = base + k;
        int c = (idx < MI) ? g_cursor[idx] : 0;
        v[k] = s;
        s += c;
    }
    int s_orig = s;
    ssum[t] = s;
    __syncthreads();
    for (int off = 1; off < 256; off <<= 1) {
        int y = (t >= off) ? ssum[t - off] : 0;
        __syncthreads();
        ssum[t] += y;
        __syncthreads();
    }
    if (t == 255) {
        __threadfence();
        atomicExch(&g_flag[b], ssum[255] + 1);   // publish (sentinel +1, 0 = not ready)
    }
    if (t == 0) {
        int off = 0;
        for (int k = 0; k < b; k++) {
            int f;
            do { f = atomicAdd(&g_flag[k], 0); } while (f == 0);
            off += f - 1;
        }
        s_off = off;
    }
    __syncthreads();
    int excl = ssum[t] - s_orig + s_off;
#pragma unroll
    for (int k = 0; k < 8; k++) {
        int idx = base + k;
        if (idx < MI) {
            int r = excl + v[k];
            g_rowptr_i[idx] = r;
            g_cursor[idx] = r;
        }
    }
    if (b == 0 && t == 0) g_rowptr_i[MI] = H;
}

// scatter second-half edges into item CSR (0-based positions in g_edges).
__global__ void scatter_edges_kernel(const int* __restrict__ rows,
                                     const int* __restrict__ cols,
                                     const float* __restrict__ vals, int H) {
    int t = blockIdx.x * blockDim.x + threadIdx.x;
    if (t >= H) return;
    int e = H + t;
    int r = __ldg(&rows[e]) - NU;
    int pos = atomicAdd(&g_cursor[r], 1);
    unsigned long long pk =
        ((unsigned long long)__float_as_uint(__ldg(&vals[e])) << 32) |
        (unsigned int)__ldg(&cols[e]);
    g_edges[pos] = pk;
}

// ---------------------------------------------------------------------------
// CSR gather SpMM (fp16 storage, fp32 accumulation), R6-proven layout:
// 8 lanes per row, 16B per lane; 4-edge groups.
// RAW=true: user rows, edges read directly from cols/vals arrays (global cols).
// RAW=false: item rows, edges from packed g_edges via g_rowptr_i.
template <bool RAW>
__global__ void spmm_kernel(const __half* __restrict__ src,
                            __half* __restrict__ dst,
                            int rowBeg, int rowEnd,
                            const int* __restrict__ cols,
                            const float* __restrict__ vals) {
    int gid = blockIdx.x * blockDim.x + threadIdx.x;
    int row = rowBeg + (gid >> 3);
    int l = gid & 7;
    if (row >= rowEnd) return;
    int beg, end;
    if (RAW) { beg = g_rowptr[row];          end = g_rowptr[row + 1]; }
    else     { beg = g_rowptr_i[row - NU];   end = g_rowptr_i[row - NU + 1]; }
    const uint4* sp = (const uint4*)src;   // 8 x uint4 per row

    float s0 = 0.f, s1 = 0.f, s2 = 0.f, s3 = 0.f,
          s4 = 0.f, s5 = 0.f, s6 = 0.f, s7 = 0.f;

#define ACCV(V, X) {                                                     \
        half2* h = (half2*)&(X);                                         \
        float2 f0 = __half22float2(h[0]);                                \
        float2 f1 = __half22float2(h[1]);                                \
        float2 f2 = __half22float2(h[2]);                                \
        float2 f3 = __half22float2(h[3]);                                \
        s0 += (V) * f0.x; s1 += (V) * f0.y; s2 += (V) * f1.x; s3 += (V) * f1.y; \
        s4 += (V) * f2.x; s5 += (V) * f2.y; s6 += (V) * f3.x; s7 += (V) * f3.y; }

    int j = beg;
    for (; j + 4 <= end; j += 4) {
        int c0, c1, c2, c3;
        float v0, v1, v2, v3;
        if (RAW) {
            c0 = __ldg(&cols[j]);     v0 = __ldg(&vals[j]);
            c1 = __ldg(&cols[j + 1]); v1 = __ldg(&vals[j + 1]);
            c2 = __ldg(&cols[j + 2]); v2 = __ldg(&vals[j + 2]);
            c3 = __ldg(&cols[j + 3]); v3 = __ldg(&vals[j + 3]);
        } else {
            unsigned long long pk0 = __ldg(&g_edges[j]);
            unsigned long long pk1 = __ldg(&g_edges[j + 1]);
            unsigned long long pk2 = __ldg(&g_edges[j + 2]);
            unsigned long long pk3 = __ldg(&g_edges[j + 3]);
            c0 = (int)(unsigned int)pk0; v0 = __uint_as_float((unsigned int)(pk0 >> 32));
            c1 = (int)(unsigned int)pk1; v1 = __uint_as_float((unsigned int)(pk1 >> 32));
            c2 = (int)(unsigned int)pk2; v2 = __uint_as_float((unsigned int)(pk2 >> 32));
            c3 = (int)(unsigned int)pk3; v3 = __uint_as_float((unsigned int)(pk3 >> 32));
        }
        uint4 x0 = __ldg(sp + c0 * 8 + l);
        uint4 x1 = __ldg(sp + c1 * 8 + l);
        uint4 x2 = __ldg(sp + c2 * 8 + l);
        uint4 x3 = __ldg(sp + c3 * 8 + l);
        ACCV(v0, x0) ACCV(v1, x1) ACCV(v2, x2) ACCV(v3, x3)
    }
    for (; j < end; j++) {
        int c; float v;
        if (RAW) { c = __ldg(&cols[j]); v = __ldg(&vals[j]); }
        else {
            unsigned long long pk = __ldg(&g_edges[j]);
            c = (int)(unsigned int)pk; v = __uint_as_float((unsigned int)(pk >> 32));
        }
        uint4 x = __ldg(sp + c * 8 + l);
        ACCV(v, x)
    }
#undef ACCV

    half2 o[4];
    o[0] = __floats2half2_rn(s0, s1);
    o[1] = __floats2half2_rn(s2, s3);
    o[2] = __floats2half2_rn(s4, s5);
    o[3] = __floats2half2_rn(s6, s7);
    ((uint4*)dst)[row * 8 + l] = *(uint4*)o;
}

// ---------------------------------------------------------------------------
// Fused layer-3 + scoring: ONE BLOCK (3 warps) PER BATCH ELEMENT.
// Per-node l3 gather: user nodes from raw cols/vals, item nodes from g_edges.
__device__ __forceinline__ void l3_gather_pk(int beg, int end, int lane,
                                             float& ax, float& ay) {
    const unsigned* sp = (const unsigned*)g_b;
    int j = beg;
    for (; j + 4 <= end; j += 4) {
        unsigned long long pk0 = __ldg(&g_edges[j]);
        unsigned long long pk1 = __ldg(&g_edges[j + 1]);
        unsigned long long pk2 = __ldg(&g_edges[j + 2]);
        unsigned long long pk3 = __ldg(&g_edges[j + 3]);
        unsigned x0 = __ldg(sp + (int)(unsigned int)pk0 * 32 + lane);
        unsigned x1 = __ldg(sp + (int)(unsigned int)pk1 * 32 + lane);
        unsigned x2 = __ldg(sp + (int)(unsigned int)pk2 * 32 + lane);
        unsigned x3 = __ldg(sp + (int)(unsigned int)pk3 * 32 + lane);
        float v0 = __uint_as_float((unsigned int)(pk0 >> 32));
        float v1 = __uint_as_float((unsigned int)(pk1 >> 32));
        float v2 = __uint_as_float((unsigned int)(pk2 >> 32));
        float v3 = __uint_as_float((unsigned int)(pk3 >> 32));
        float2 f0 = __half22float2(*(half2*)&x0);
        float2 f1 = __half22float2(*(half2*)&x1);
        float2 f2 = __half22float2(*(half2*)&x2);
        float2 f3 = __half22float2(*(half2*)&x3);
        ax += v0 * f0.x; ay += v0 * f0.y;
        ax += v1 * f1.x; ay += v1 * f1.y;
        ax += v2 * f2.x; ay += v2 * f2.y;
        ax += v3 * f3.x; ay += v3 * f3.y;
    }
    for (; j < end; j++) {
        unsigned long long pk = __ldg(&g_edges[j]);
        unsigned x = __ldg(sp + (int)(unsigned int)pk * 32 + lane);
        float v = __uint_as_float((unsigned int)(pk >> 32));
        float2 f = __half22float2(*(half2*)&x);
        ax += v * f.x; ay += v * f.y;
    }
}

__device__ __forceinline__ void l3_gather_raw(int beg, int end, int lane,
                                              const int* __restrict__ cols,
                                              const float* __restrict__ vals,
                                              float& ax, float& ay) {
    const unsigned* sp = (const unsigned*)g_b;
    int j = beg;
    for (; j + 4 <= end; j += 4) {
        int c0 = __ldg(&cols[j]);     float v0 = __ldg(&vals[j]);
        int c1 = __ldg(&cols[j + 1]); float v1 = __ldg(&vals[j + 1]);
        int c2 = __ldg(&cols[j + 2]); float v2 = __ldg(&vals[j + 2]);
        int c3 = __ldg(&cols[j + 3]); float v3 = __ldg(&vals[j + 3]);
        unsigned x0 = __ldg(sp + c0 * 32 + lane);
        unsigned x1 = __ldg(sp + c1 * 32 + lane);
        unsigned x2 = __ldg(sp + c2 * 32 + lane);
        unsigned x3 = __ldg(sp + c3 * 32 + lane);
        float2 f0 = __half22float2(*(half2*)&x0);
        float2 f1 = __half22float2(*(half2*)&x1);
        float2 f2 = __half22float2(*(half2*)&x2);
        float2 f3 = __half22float2(*(half2*)&x3);
        ax += v0 * f0.x; ay += v0 * f0.y;
        ax += v1 * f1.x; ay += v1 * f1.y;
        ax += v2 * f2.x; ay += v2 * f2.y;
        ax += v3 * f3.x; ay += v3 * f3.y;
    }
    for (; j < end; j++) {
        int c = __ldg(&cols[j]); float v = __ldg(&vals[j]);
        unsigned x = __ldg(sp + c * 32 + lane);
        float2 f = __half22float2(*(half2*)&x);
        ax += v * f.x; ay += v * f.y;
    }
}

__global__ void final_kernel(const float* __restrict__ eu0,
                             const float* __restrict__ ei0,
                             const int* __restrict__ cols,
                             const float* __restrict__ vals,
                             const int* __restrict__ user,
                             const int* __restrict__ item_i,
                             const int* __restrict__ item_j,
                             float* __restrict__ out, int B) {
    __shared__ float sm[3][64];
    __shared__ float regp[3];
    int bidx = blockIdx.x;
    int w = threadIdx.x >> 5;
    int lane = threadIdx.x & 31;
    if (bidx >= B) return;

    float ax, ay, sq;
    if (w == 0) {
        int u = __ldg(&user[bidx]);
        float2 v0 = __ldg((const float2*)eu0 + u * 32 + lane);
        ax = v0.x; ay = v0.y; sq = v0.x * v0.x + v0.y * v0.y;
        float2 t;
        t = __half22float2(((const half2*)g_a)[u * 32 + lane]); ax += t.x; ay += t.y;
        t = __half22float2(((const half2*)g_b)[u * 32 + lane]); ax += t.x; ay += t.y;
        l3_gather_raw(g_rowptr[u], g_rowptr[u + 1], lane, cols, vals, ax, ay);
    } else {
        int it = (w == 1) ? __ldg(&item_i[bidx]) : __ldg(&item_j[bidx]);
        int n = NU + it;
        float2 v0 = __ldg((const float2*)ei0 + it * 32 + lane);
        ax = v0.x; ay = v0.y; sq = v0.x * v0.x + v0.y * v0.y;
        float2 t;
        t = __half22float2(((const half2*)g_a)[n * 32 + lane]); ax += t.x; ay += t.y;
        t = __half22float2(((const half2*)g_b)[n * 32 + lane]); ax += t.x; ay += t.y;
        l3_gather_pk(g_rowptr_i[it], g_rowptr_i[it + 1], lane, ax, ay);
    }
    sm[w][2 * lane] = ax;
    sm[w][2 * lane + 1] = ay;
#pragma unroll
    for (int o = 16; o; o >>= 1) sq += __shfl_xor_sync(0xFFFFFFFFu, sq, o);
    if (lane == 0) regp[w] = sq;
    __syncthreads();

    if (w == 0) {
        float p = sm[0][2 * lane] * sm[1][2 * lane]
                + sm[0][2 * lane + 1] * sm[1][2 * lane + 1];
#pragma unroll
        for (int o = 16; o; o >>= 1) p += __shfl_xor_sync(0xFFFFFFFFu, p, o);
        if (lane == 0) out[bidx] = p * (1.f / 16.f);
    } else if (w == 1) {
        float p = sm[0][2 * lane] * sm[2][2 * lane]
                + sm[0][2 * lane + 1] * sm[2][2 * lane + 1];
#pragma unroll
        for (int o = 16; o; o >>= 1) p += __shfl_xor_sync(0xFFFFFFFFu, p, o);
        if (lane == 0) out[B + bidx] = p * (1.f / 16.f);
    } else {
        if (lane == 0) {
            float reg = regp[0] + regp[1] + regp[2];
            atomicAdd(out + 2 * B, reg * (0.5f / (float)B));
        }
    }
}

// ---------------------------------------------------------------------------
extern "C" void kernel_launch(void* const* d_in, const int* in_sizes, int n_in,
                              void* d_out, int out_size) {
    const float* eu0    = (const float*)d_in[0];
    const float* ei0    = (const float*)d_in[1];
    const int*   rows   = (const int*)d_in[2];
    const int*   cols   = (const int*)d_in[3];
    const float* vals   = (const float*)d_in[4];
    const int*   user   = (const int*)d_in[5];
    const int*   item_i = (const int*)d_in[6];
    const int*   item_j = (const int*)d_in[7];

    int E = in_sizes[2];
    int H = E / 2;          // first half: user rows (sorted); second: item rows
    int B = in_sizes[5];
    float* out = (float*)d_out;

    __half *ph0, *pa, *pb;
    cudaGetSymbolAddress((void**)&ph0, g_h0);
    cudaGetSymbolAddress((void**)&pa, g_a);
    cudaGetSymbolAddress((void**)&pb, g_b);

    const int T = 256;
    int ugrid = (NU * 8 + T - 1) / T;   // user-row spmm
    int igrid = (MI * 8 + T - 1) / T;   // item-row spmm
    int cgrid = (MI + T - 1) / T;       // clear

    if (g_sr.ok) {
        cudaStream_t s = g_sr.side;
        cudaEventRecord(g_sr.eFork, 0);
        cudaStreamWaitEvent(s, g_sr.eFork, 0);

        // side: convert (no deps)
        convert_init_kernel<<<(ND4 + T - 1) / T, T, 0, s>>>(
            (const float4*)eu0, (const float4*)ei0, out, B);
        cudaEventRecord(g_sr.eConv, s);

        // main: item CSR build chain (no user-half copy anymore)
        hist_kernel<<<(H + T - 1) / T, T>>>(rows, H);
        cudaEventRecord(g_sr.eHist, 0);
        scan_fused_kernel<<<NBLK_I, 256>>>(H);
        scatter_edges_kernel<<<(H + T - 1) / T, T>>>(rows, cols, vals, H);
        cudaEventRecord(g_sr.eScat, 0);

        // side: L1 user rows (convert same-stream + user rowptr [eHist])
        cudaStreamWaitEvent(s, g_sr.eHist, 0);
        spmm_kernel<true><<<ugrid, T, 0, s>>>(ph0, pa, 0, NU, cols, vals);
        cudaEventRecord(g_sr.eL1u, s);
        // side: tail clears (cursors last used by scatter [eScat]; flags by scan)
        cudaStreamWaitEvent(s, g_sr.eScat, 0);
        clear_kernel<<<cgrid, T, 0, s>>>();
        cudaEventRecord(g_sr.eSide, s);

        // main: L1 item rows (convert [eConv] + scatter same-stream)
        cudaStreamWaitEvent(0, g_sr.eConv, 0);
        spmm_kernel<false><<<igrid, T>>>(ph0, pa, NU, NN, cols, vals);
        // main: L2 item rows (needs L1_user [eL1u]; reads g_a user cols)
        cudaStreamWaitEvent(0, g_sr.eL1u, 0);
        spmm_kernel<false><<<igrid, T>>>(pa, pb, NU, NN, cols, vals);
        // main: L2 user rows (needs L1_item, same stream; reads g_a item cols)
        spmm_kernel<true><<<ugrid, T>>>(pa, pb, 0, NU, cols, vals);

        // join side, then fused layer-3 + scoring
        cudaStreamWaitEvent(0, g_sr.eSide, 0);
        final_kernel<<<B, 96>>>(eu0, ei0, cols, vals, user, item_i, item_j, out, B);
    } else {
        // serial fallback (single stream)
        convert_init_kernel<<<(ND4 + T - 1) / T, T>>>(
            (const float4*)eu0, (const float4*)ei0, out, B);
        hist_kernel<<<(H + T - 1) / T, T>>>(rows, H);
        scan_fused_kernel<<<NBLK_I, 256>>>(H);
        scatter_edges_kernel<<<(H + T - 1) / T, T>>>(rows, cols, vals, H);
        spmm_kernel<true ><<<ugrid, T>>>(ph0, pa, 0, NU, cols, vals);
        spmm_kernel<false><<<igrid, T>>>(ph0, pa, NU, NN, cols, vals);
        spmm_kernel<false><<<igrid, T>>>(pa, pb, NU, NN, cols, vals);
        spmm_kernel<true ><<<ugrid, T>>>(pa, pb, 0, NU, cols, vals);
        clear_kernel<<<cgrid, T>>>();
        final_kernel<<<B, 96>>>(eu0, ei0, cols, vals, user, item_i, item_j, out, B);
    }
}

// round 15
// speedup vs baseline: 1.0290x; 1.0290x over previous
#include <cuda_runtime.h>
#include <cuda_fp16.h>

#define NU 100000
#define MI 50000
#define NN (NU + MI)
#define D 64
#define ND (NN * D)
#define ND4 (ND / 4)
#define MAXE 2000000
#define CHUNK 2048
#define NBLK_I ((MI + CHUNK - 1) / CHUNK)   // 25

// Static scratch (no dynamic allocation allowed).
static __device__ __half g_h0[ND];                    // fp16 copy of concat(eu0, ei0)
static __device__ __half g_a[ND];                     // layer 1 out (fp16)
static __device__ __half g_b[ND];                     // layer 2 out (fp16)
static __device__ unsigned long long g_edges[MAXE];   // ITEM half only: {val:f32, col:u32}
static __device__ int g_rowptr[NU + 1];               // user CSR into cols/vals arrays
static __device__ int g_rowptr_i[MI + 1];             // item CSR into g_edges (0-based)
static __device__ int g_cursor[MI];                   // zero at entry; rebuilt+rezeroed
static __device__ int g_blocksum[NBLK_I];             // scan stage-1 block totals

// ---------------------------------------------------------------------------
struct StreamRes {
    cudaStream_t side = nullptr;
    cudaEvent_t eFork = nullptr, eHist = nullptr, eConv = nullptr,
                eScat = nullptr, eSide = nullptr;
    bool ok = false;
    StreamRes() {
        if (cudaStreamCreateWithFlags(&side, cudaStreamNonBlocking) != cudaSuccess) return;
        if (cudaEventCreateWithFlags(&eFork, cudaEventDisableTiming) != cudaSuccess) return;
        if (cudaEventCreateWithFlags(&eHist, cudaEventDisableTiming) != cudaSuccess) return;
        if (cudaEventCreateWithFlags(&eConv, cudaEventDisableTiming) != cudaSuccess) return;
        if (cudaEventCreateWithFlags(&eScat, cudaEventDisableTiming) != cudaSuccess) return;
        if (cudaEventCreateWithFlags(&eSide, cudaEventDisableTiming) != cudaSuccess) return;
        ok = true;
    }
};
static StreamRes g_sr;

// ---------------------------------------------------------------------------
// convert inputs to fp16 table; out[2B] = 0
__global__ void convert_init_kernel(const float4* __restrict__ eu,
                                    const float4* __restrict__ ei,
                                    float* __restrict__ out, int B) {
    int i = blockIdx.x * blockDim.x + threadIdx.x;
    if (i < ND4) {
        const int NU4 = NU * D / 4;
        float4 v = (i < NU4) ? __ldg(eu + i) : __ldg(ei + (i - NU4));
        half2 h[2];
        h[0] = __floats2half2_rn(v.x, v.y);
        h[1] = __floats2half2_rn(v.z, v.w);
        ((uint2*)g_h0)[i] = *(uint2*)h;
    }
    if (i == 0) out[2 * B] = 0.f;
}

// re-zero item cursors (tail of launch; entry state is always zero)
__global__ void clear_kernel() {
    int i = blockIdx.x * blockDim.x + threadIdx.x;
    if (i < MI) g_cursor[i] = 0;
}

// user rowptr boundary detection (first half, sorted) + item-degree histogram.
// NO edge copy — user CSR edges ARE cols/vals[0..H).
__global__ void hist_kernel(const int* __restrict__ rows, int H) {
    int e = blockIdx.x * blockDim.x + threadIdx.x;
    if (e >= H) return;
    int cur = __ldg(&rows[e]);
    int prev = (e == 0) ? -1 : __ldg(&rows[e - 1]);
    for (int r = prev + 1; r <= cur; r++) g_rowptr[r] = e;
    if (e == H - 1)
        for (int r = cur + 1; r <= NU; r++) g_rowptr[r] = H;
    atomicAdd(&g_cursor[__ldg(&rows[H + e]) - NU], 1);
}

// multi-block item scan, stage 1 (R10/R11-proven): per-chunk exclusive scan,
// chunk-local prefixes into g_rowptr_i slots + block totals.
__global__ void scan1_kernel() {
    __shared__ int ssum[256];
    int b = blockIdx.x, t = threadIdx.x;
    int base = b * CHUNK + t * 8;
    int v[8];
    int s = 0;
#pragma unroll
    for (int k = 0; k < 8; k++) {
        int idx = base + k;
        int c = (idx < MI) ? g_cursor[idx] : 0;
        v[k] = s;
        s += c;
    }
    int s_orig = s;
    ssum[t] = s;
    __syncthreads();
    for (int off = 1; off < 256; off <<= 1) {
        int y = (t >= off) ? ssum[t - off] : 0;
        __syncthreads();
        ssum[t] += y;
        __syncthreads();
    }
    int excl = ssum[t] - s_orig;
#pragma unroll
    for (int k = 0; k < 8; k++) {
        int idx = base + k;
        if (idx < MI) g_rowptr_i[idx] = excl + v[k];
    }
    if (t == 255) g_blocksum[b] = ssum[255];
}

// stage 2: add per-block prefix (each block sums <=25 cached totals);
// initialize cursors; cap rowptr. No inter-block synchronization.
__global__ void scan2_kernel(int H) {
    int b = blockIdx.x, t = threadIdx.x;
    int off = 0;
    for (int k = 0; k < b; k++) off += g_blocksum[k];
    int base = b * CHUNK + t * 8;
#pragma unroll
    for (int k = 0; k < 8; k++) {
        int idx = base + k;
        if (idx < MI) {
            int r = g_rowptr_i[idx] + off;
            g_rowptr_i[idx] = r;
            g_cursor[idx] = r;
        }
    }
    if (b == 0 && t == 0) g_rowptr_i[MI] = H;
}

// scatter second-half edges into item CSR (0-based positions in g_edges).
__global__ void scatter_edges_kernel(const int* __restrict__ rows,
                                     const int* __restrict__ cols,
                                     const float* __restrict__ vals, int H) {
    int t = blockIdx.x * blockDim.x + threadIdx.x;
    if (t >= H) return;
    int e = H + t;
    int r = __ldg(&rows[e]) - NU;
    int pos = atomicAdd(&g_cursor[r], 1);
    unsigned long long pk =
        ((unsigned long long)__float_as_uint(__ldg(&vals[e])) << 32) |
        (unsigned int)__ldg(&cols[e]);
    g_edges[pos] = pk;
}

// ---------------------------------------------------------------------------
// CSR gather SpMM (fp16 storage, fp32 accumulation), R6-proven layout:
// 8 lanes per row, 16B per lane; 4-edge groups.
// RAW=true: user rows, edges read directly from cols/vals arrays.
// RAW=false: item rows, edges from packed g_edges via g_rowptr_i.
template <bool RAW>
__global__ void spmm_kernel(const __half* __restrict__ src,
                            __half* __restrict__ dst,
                            int rowBeg, int rowEnd,
                            const int* __restrict__ cols,
                            const float* __restrict__ vals) {
    int gid = blockIdx.x * blockDim.x + threadIdx.x;
    int row = rowBeg + (gid >> 3);
    int l = gid & 7;
    if (row >= rowEnd) return;
    int beg, end;
    if (RAW) { beg = g_rowptr[row];          end = g_rowptr[row + 1]; }
    else     { beg = g_rowptr_i[row - NU];   end = g_rowptr_i[row - NU + 1]; }
    const uint4* sp = (const uint4*)src;   // 8 x uint4 per row

    float s0 = 0.f, s1 = 0.f, s2 = 0.f, s3 = 0.f,
          s4 = 0.f, s5 = 0.f, s6 = 0.f, s7 = 0.f;

#define ACCV(V, X) {                                                     \
        half2* h = (half2*)&(X);                                         \
        float2 f0 = __half22float2(h[0]);                                \
        float2 f1 = __half22float2(h[1]);                                \
        float2 f2 = __half22float2(h[2]);                                \
        float2 f3 = __half22float2(h[3]);                                \
        s0 += (V) * f0.x; s1 += (V) * f0.y; s2 += (V) * f1.x; s3 += (V) * f1.y; \
        s4 += (V) * f2.x; s5 += (V) * f2.y; s6 += (V) * f3.x; s7 += (V) * f3.y; }

    int j = beg;
    for (; j + 4 <= end; j += 4) {
        int c0, c1, c2, c3;
        float v0, v1, v2, v3;
        if (RAW) {
            c0 = __ldg(&cols[j]);     v0 = __ldg(&vals[j]);
            c1 = __ldg(&cols[j + 1]); v1 = __ldg(&vals[j + 1]);
            c2 = __ldg(&cols[j + 2]); v2 = __ldg(&vals[j + 2]);
            c3 = __ldg(&cols[j + 3]); v3 = __ldg(&vals[j + 3]);
        } else {
            unsigned long long pk0 = __ldg(&g_edges[j]);
            unsigned long long pk1 = __ldg(&g_edges[j + 1]);
            unsigned long long pk2 = __ldg(&g_edges[j + 2]);
            unsigned long long pk3 = __ldg(&g_edges[j + 3]);
            c0 = (int)(unsigned int)pk0; v0 = __uint_as_float((unsigned int)(pk0 >> 32));
            c1 = (int)(unsigned int)pk1; v1 = __uint_as_float((unsigned int)(pk1 >> 32));
            c2 = (int)(unsigned int)pk2; v2 = __uint_as_float((unsigned int)(pk2 >> 32));
            c3 = (int)(unsigned int)pk3; v3 = __uint_as_float((unsigned int)(pk3 >> 32));
        }
        uint4 x0 = __ldg(sp + c0 * 8 + l);
        uint4 x1 = __ldg(sp + c1 * 8 + l);
        uint4 x2 = __ldg(sp + c2 * 8 + l);
        uint4 x3 = __ldg(sp + c3 * 8 + l);
        ACCV(v0, x0) ACCV(v1, x1) ACCV(v2, x2) ACCV(v3, x3)
    }
    for (; j < end; j++) {
        int c; float v;
        if (RAW) { c = __ldg(&cols[j]); v = __ldg(&vals[j]); }
        else {
            unsigned long long pk = __ldg(&g_edges[j]);
            c = (int)(unsigned int)pk; v = __uint_as_float((unsigned int)(pk >> 32));
        }
        uint4 x = __ldg(sp + c * 8 + l);
        ACCV(v, x)
    }
#undef ACCV

    half2 o[4];
    o[0] = __floats2half2_rn(s0, s1);
    o[1] = __floats2half2_rn(s2, s3);
    o[2] = __floats2half2_rn(s4, s5);
    o[3] = __floats2half2_rn(s6, s7);
    ((uint4*)dst)[row * 8 + l] = *(uint4*)o;
}

// ---------------------------------------------------------------------------
// Fused layer-3 + scoring: ONE BLOCK (3 warps) PER BATCH ELEMENT.
__device__ __forceinline__ void l3_gather_pk(int beg, int end, int lane,
                                             float& ax, float& ay) {
    const unsigned* sp = (const unsigned*)g_b;
    int j = beg;
    for (; j + 4 <= end; j += 4) {
        unsigned long long pk0 = __ldg(&g_edges[j]);
        unsigned long long pk1 = __ldg(&g_edges[j + 1]);
        unsigned long long pk2 = __ldg(&g_edges[j + 2]);
        unsigned long long pk3 = __ldg(&g_edges[j + 3]);
        unsigned x0 = __ldg(sp + (int)(unsigned int)pk0 * 32 + lane);
        unsigned x1 = __ldg(sp + (int)(unsigned int)pk1 * 32 + lane);
        unsigned x2 = __ldg(sp + (int)(unsigned int)pk2 * 32 + lane);
        unsigned x3 = __ldg(sp + (int)(unsigned int)pk3 * 32 + lane);
        float v0 = __uint_as_float((unsigned int)(pk0 >> 32));
        float v1 = __uint_as_float((unsigned int)(pk1 >> 32));
        float v2 = __uint_as_float((unsigned int)(pk2 >> 32));
        float v3 = __uint_as_float((unsigned int)(pk3 >> 32));
        float2 f0 = __half22float2(*(half2*)&x0);
        float2 f1 = __half22float2(*(half2*)&x1);
        float2 f2 = __half22float2(*(half2*)&x2);
        float2 f3 = __half22float2(*(half2*)&x3);
        ax += v0 * f0.x; ay += v0 * f0.y;
        ax += v1 * f1.x; ay += v1 * f1.y;
        ax += v2 * f2.x; ay += v2 * f2.y;
        ax += v3 * f3.x; ay += v3 * f3.y;
    }
    for (; j < end; j++) {
        unsigned long long pk = __ldg(&g_edges[j]);
        unsigned x = __ldg(sp + (int)(unsigned int)pk * 32 + lane);
        float v = __uint_as_float((unsigned int)(pk >> 32));
        float2 f = __half22float2(*(half2*)&x);
        ax += v * f.x; ay += v * f.y;
    }
}

__device__ __forceinline__ void l3_gather_raw(int beg, int end, int lane,
                                              const int* __restrict__ cols,
                                              const float* __restrict__ vals,
                                              float& ax, float& ay) {
    const unsigned* sp = (const unsigned*)g_b;
    int j = beg;
    for (; j + 4 <= end; j += 4) {
        int c0 = __ldg(&cols[j]);     float v0 = __ldg(&vals[j]);
        int c1 = __ldg(&cols[j + 1]); float v1 = __ldg(&vals[j + 1]);
        int c2 = __ldg(&cols[j + 2]); float v2 = __ldg(&vals[j + 2]);
        int c3 = __ldg(&cols[j + 3]); float v3 = __ldg(&vals[j + 3]);
        unsigned x0 = __ldg(sp + c0 * 32 + lane);
        unsigned x1 = __ldg(sp + c1 * 32 + lane);
        unsigned x2 = __ldg(sp + c2 * 32 + lane);
        unsigned x3 = __ldg(sp + c3 * 32 + lane);
        float2 f0 = __half22float2(*(half2*)&x0);
        float2 f1 = __half22float2(*(half2*)&x1);
        float2 f2 = __half22float2(*(half2*)&x2);
        float2 f3 = __half22float2(*(half2*)&x3);
        ax += v0 * f0.x; ay += v0 * f0.y;
        ax += v1 * f1.x; ay += v1 * f1.y;
        ax += v2 * f2.x; ay += v2 * f2.y;
        ax += v3 * f3.x; ay += v3 * f3.y;
    }
    for (; j < end; j++) {
        int c = __ldg(&cols[j]); float v = __ldg(&vals[j]);
        unsigned x = __ldg(sp + c * 32 + lane);
        float2 f = __half22float2(*(half2*)&x);
        ax += v * f.x; ay += v * f.y;
    }
}

__global__ void final_kernel(const float* __restrict__ eu0,
                             const float* __restrict__ ei0,
                             const int* __restrict__ cols,
                             const float* __restrict__ vals,
                             const int* __restrict__ user,
                             const int* __restrict__ item_i,
                             const int* __restrict__ item_j,
                             float* __restrict__ out, int B) {
    __shared__ float sm[3][64];
    __shared__ float regp[3];
    int bidx = blockIdx.x;
    int w = threadIdx.x >> 5;
    int lane = threadIdx.x & 31;
    if (bidx >= B) return;

    float ax, ay, sq;
    if (w == 0) {
        int u = __ldg(&user[bidx]);
        float2 v0 = __ldg((const float2*)eu0 + u * 32 + lane);
        ax = v0.x; ay = v0.y; sq = v0.x * v0.x + v0.y * v0.y;
        float2 t;
        t = __half22float2(((const half2*)g_a)[u * 32 + lane]); ax += t.x; ay += t.y;
        t = __half22float2(((const half2*)g_b)[u * 32 + lane]); ax += t.x; ay += t.y;
        l3_gather_raw(g_rowptr[u], g_rowptr[u + 1], lane, cols, vals, ax, ay);
    } else {
        int it = (w == 1) ? __ldg(&item_i[bidx]) : __ldg(&item_j[bidx]);
        int n = NU + it;
        float2 v0 = __ldg((const float2*)ei0 + it * 32 + lane);
        ax = v0.x; ay = v0.y; sq = v0.x * v0.x + v0.y * v0.y;
        float2 t;
        t = __half22float2(((const half2*)g_a)[n * 32 + lane]); ax += t.x; ay += t.y;
        t = __half22float2(((const half2*)g_b)[n * 32 + lane]); ax += t.x; ay += t.y;
        l3_gather_pk(g_rowptr_i[it], g_rowptr_i[it + 1], lane, ax, ay);
    }
    sm[w][2 * lane] = ax;
    sm[w][2 * lane + 1] = ay;
#pragma unroll
    for (int o = 16; o; o >>= 1) sq += __shfl_xor_sync(0xFFFFFFFFu, sq, o);
    if (lane == 0) regp[w] = sq;
    __syncthreads();

    if (w == 0) {
        float p = sm[0][2 * lane] * sm[1][2 * lane]
                + sm[0][2 * lane + 1] * sm[1][2 * lane + 1];
#pragma unroll
        for (int o = 16; o; o >>= 1) p += __shfl_xor_sync(0xFFFFFFFFu, p, o);
        if (lane == 0) out[bidx] = p * (1.f / 16.f);
    } else if (w == 1) {
        float p = sm[0][2 * lane] * sm[2][2 * lane]
                + sm[0][2 * lane + 1] * sm[2][2 * lane + 1];
#pragma unroll
        for (int o = 16; o; o >>= 1) p += __shfl_xor_sync(0xFFFFFFFFu, p, o);
        if (lane == 0) out[B + bidx] = p * (1.f / 16.f);
    } else {
        if (lane == 0) {
            float reg = regp[0] + regp[1] + regp[2];
            atomicAdd(out + 2 * B, reg * (0.5f / (float)B));
        }
    }
}

// ---------------------------------------------------------------------------
extern "C" void kernel_launch(void* const* d_in, const int* in_sizes, int n_in,
                              void* d_out, int out_size) {
    const float* eu0    = (const float*)d_in[0];
    const float* ei0    = (const float*)d_in[1];
    const int*   rows   = (const int*)d_in[2];
    const int*   cols   = (const int*)d_in[3];
    const float* vals   = (const float*)d_in[4];
    const int*   user   = (const int*)d_in[5];
    const int*   item_i = (const int*)d_in[6];
    const int*   item_j = (const int*)d_in[7];

    int E = in_sizes[2];
    int H = E / 2;          // first half: user rows (sorted); second: item rows
    int B = in_sizes[5];
    float* out = (float*)d_out;

    __half *ph0, *pa, *pb;
    cudaGetSymbolAddress((void**)&ph0, g_h0);
    cudaGetSymbolAddress((void**)&pa, g_a);
    cudaGetSymbolAddress((void**)&pb, g_b);

    const int T = 256;
    int ugrid = (NU * 8 + T - 1) / T;   // user-row spmm
    int igrid = (MI * 8 + T - 1) / T;   // item-row spmm
    int cgrid = (MI + T - 1) / T;       // clear

    if (g_sr.ok) {
        cudaStream_t s = g_sr.side;
        cudaEventRecord(g_sr.eFork, 0);
        cudaStreamWaitEvent(s, g_sr.eFork, 0);

        // side: convert (no deps)
        convert_init_kernel<<<(ND4 + T - 1) / T, T, 0, s>>>(
            (const float4*)eu0, (const float4*)ei0, out, B);
        cudaEventRecord(g_sr.eConv, s);

        // main: item CSR build chain (two-kernel scan, no device-side spinning)
        hist_kernel<<<(H + T - 1) / T, T>>>(rows, H);
        cudaEventRecord(g_sr.eHist, 0);
        scan1_kernel<<<NBLK_I, 256>>>();
        scan2_kernel<<<NBLK_I, 256>>>(H);
        scatter_edges_kernel<<<(H + T - 1) / T, T>>>(rows, cols, vals, H);
        cudaEventRecord(g_sr.eScat, 0);

        // side: L1 user rows (convert same-stream + user rowptr [eHist])
        cudaStreamWaitEvent(s, g_sr.eHist, 0);
        spmm_kernel<true><<<ugrid, T, 0, s>>>(ph0, pa, 0, NU, cols, vals);
        // side: L2 item rows (reads g_a USER cols = L1_user same-stream; item CSR [eScat])
        cudaStreamWaitEvent(s, g_sr.eScat, 0);
        spmm_kernel<false><<<igrid, T, 0, s>>>(pa, pb, NU, NN, cols, vals);
        // side: tail clear (cursors last used by scatter [eScat, already waited])
        clear_kernel<<<cgrid, T, 0, s>>>();
        cudaEventRecord(g_sr.eSide, s);

        // main: L1 item rows (convert [eConv] + scatter same-stream)
        cudaStreamWaitEvent(0, g_sr.eConv, 0);
        spmm_kernel<false><<<igrid, T>>>(ph0, pa, NU, NN, cols, vals);
        // main: L2 user rows (reads g_a ITEM cols = L1_item same-stream; user rowptr done)
        spmm_kernel<true><<<ugrid, T>>>(pa, pb, 0, NU, cols, vals);

        // join side, then fused layer-3 + scoring
        cudaStreamWaitEvent(0, g_sr.eSide, 0);
        final_kernel<<<B, 96>>>(eu0, ei0, cols, vals, user, item_i, item_j, out, B);
    } else {
        // serial fallback (single stream)
        convert_init_kernel<<<(ND4 + T - 1) / T, T>>>(
            (const float4*)eu0, (const float4*)ei0, out, B);
        hist_kernel<<<(H + T - 1) / T, T>>>(rows, H);
        scan1_kernel<<<NBLK_I, 256>>>();
        scan2_kernel<<<NBLK_I, 256>>>(H);
        scatter_edges_kernel<<<(H + T - 1) / T, T>>>(rows, cols, vals, H);
        spmm_kernel<true ><<<ugrid, T>>>(ph0, pa, 0, NU, cols, vals);
        spmm_kernel<false><<<igrid, T>>>(ph0, pa, NU, NN, cols, vals);
        spmm_kernel<false><<<igrid, T>>>(pa, pb, NU, NN, cols, vals);
        spmm_kernel<true ><<<ugrid, T>>>(pa, pb, 0, NU, cols, vals);
        clear_kernel<<<cgrid, T>>>();
        final_kernel<<<B, 96>>>(eu0, ei0, cols, vals, user, item_i, item_j, out, B);
    }
}

// round 16
// speedup vs baseline: 1.0441x; 1.0147x over previous
#include <cuda_runtime.h>
#include <cuda_fp16.h>

#define NU 100000
#define MI 50000
#define NN (NU + MI)
#define D 64
#define ND (NN * D)
#define MAXE 2000000
#define MAXB 16384
#define CHUNK 2048
#define NBLK_I ((MI + CHUNK - 1) / CHUNK)   // 25

// Static scratch (no dynamic allocation allowed).
static __device__ __half g_a[ND];                     // layer 1 out (fp16)
static __device__ __half g_b[ND];                     // layer 2 out (fp16)
static __device__ unsigned long long g_edges[MAXE];   // ITEM half only: {val:f32, col:u32}
static __device__ int g_rowptr[NU + 1];               // user CSR into cols/vals arrays
static __device__ int g_rowptr_i[MI + 1];             // item CSR into g_edges (0-based)
static __device__ int g_cursor[MI];                   // zero at entry; rebuilt+rezeroed
static __device__ int g_blocksum[NBLK_I];             // scan stage-1 block totals
static __device__ float g_s[MAXB * D];                // user-node partial accum vectors
static __device__ float g_sreg[MAXB];                 // user-node reg-loss partials

// ---------------------------------------------------------------------------
struct StreamRes {
    cudaStream_t side = nullptr;
    cudaEvent_t eFork = nullptr, eHist = nullptr, eScat = nullptr, eSide = nullptr;
    bool ok = false;
    StreamRes() {
        if (cudaStreamCreateWithFlags(&side, cudaStreamNonBlocking) != cudaSuccess) return;
        if (cudaEventCreateWithFlags(&eFork, cudaEventDisableTiming) != cudaSuccess) return;
        if (cudaEventCreateWithFlags(&eHist, cudaEventDisableTiming) != cudaSuccess) return;
        if (cudaEventCreateWithFlags(&eScat, cudaEventDisableTiming) != cudaSuccess) return;
        if (cudaEventCreateWithFlags(&eSide, cudaEventDisableTiming) != cudaSuccess) return;
        ok = true;
    }
};
static StreamRes g_sr;

// ---------------------------------------------------------------------------
// re-zero item cursors (tail of launch; entry state is always zero)
__global__ void clear_kernel() {
    int i = blockIdx.x * blockDim.x + threadIdx.x;
    if (i < MI) g_cursor[i] = 0;
}

// user rowptr boundary detection (first half, sorted) + item-degree histogram.
// Also zeroes out[2B] (must precede final_join's atomicAdd — same stream).
__global__ void hist_kernel(const int* __restrict__ rows, int H,
                            float* __restrict__ out, int B) {
    int e = blockIdx.x * blockDim.x + threadIdx.x;
    if (e == 0) out[2 * B] = 0.f;
    if (e >= H) return;
    int cur = __ldg(&rows[e]);
    int prev = (e == 0) ? -1 : __ldg(&rows[e - 1]);
    for (int r = prev + 1; r <= cur; r++) g_rowptr[r] = e;
    if (e == H - 1)
        for (int r = cur + 1; r <= NU; r++) g_rowptr[r] = H;
    atomicAdd(&g_cursor[__ldg(&rows[H + e]) - NU], 1);
}

// multi-block item scan, stage 1: per-chunk exclusive scan + block totals.
__global__ void scan1_kernel() {
    __shared__ int ssum[256];
    int b = blockIdx.x, t = threadIdx.x;
    int base = b * CHUNK + t * 8;
    int v[8];
    int s = 0;
#pragma unroll
    for (int k = 0; k < 8; k++) {
        int idx = base + k;
        int c = (idx < MI) ? g_cursor[idx] : 0;
        v[k] = s;
        s += c;
    }
    int s_orig = s;
    ssum[t] = s;
    __syncthreads();
    for (int off = 1; off < 256; off <<= 1) {
        int y = (t >= off) ? ssum[t - off] : 0;
        __syncthreads();
        ssum[t] += y;
        __syncthreads();
    }
    int excl = ssum[t] - s_orig;
#pragma unroll
    for (int k = 0; k < 8; k++) {
        int idx = base + k;
        if (idx < MI) g_rowptr_i[idx] = excl + v[k];
    }
    if (t == 255) g_blocksum[b] = ssum[255];
}

// stage 2: add per-block prefix; initialize cursors; cap rowptr.
__global__ void scan2_kernel(int H) {
    int b = blockIdx.x, t = threadIdx.x;
    int off = 0;
    for (int k = 0; k < b; k++) off += g_blocksum[k];
    int base = b * CHUNK + t * 8;
#pragma unroll
    for (int k = 0; k < 8; k++) {
        int idx = base + k;
        if (idx < MI) {
            int r = g_rowptr_i[idx] + off;
            g_rowptr_i[idx] = r;
            g_cursor[idx] = r;
        }
    }
    if (b == 0 && t == 0) g_rowptr_i[MI] = H;
}

// scatter second-half edges into item CSR (0-based positions in g_edges).
__global__ void scatter_edges_kernel(const int* __restrict__ rows,
                                     const int* __restrict__ cols,
                                     const float* __restrict__ vals, int H) {
    int t = blockIdx.x * blockDim.x + threadIdx.x;
    if (t >= H) return;
    int e = H + t;
    int r = __ldg(&rows[e]) - NU;
    int pos = atomicAdd(&g_cursor[r], 1);
    unsigned long long pk =
        ((unsigned long long)__float_as_uint(__ldg(&vals[e])) << 32) |
        (unsigned int)__ldg(&cols[e]);
    g_edges[pos] = pk;
}

// ---------------------------------------------------------------------------
// LAYER-1 SpMM: gathers fp32 input table directly (R3-proven 16 lanes/row,
// float4 per lane), writes fp16. Bipartite: user rows gather ONLY ei0
// (col-NU), item rows gather ONLY eu0.
// RAW=true: user rows, raw cols/vals. RAW=false: item rows, packed g_edges.
template <bool RAW>
__global__ void spmm_l1_kernel(const float* __restrict__ srcTab,
                               __half* __restrict__ dst,
                               int rowBeg, int rowEnd,
                               const int* __restrict__ cols,
                               const float* __restrict__ vals) {
    int gid = blockIdx.x * blockDim.x + threadIdx.x;
    int row = rowBeg + (gid >> 4);
    int l = gid & 15;
    if (row >= rowEnd) return;
    int beg, end;
    if (RAW) { beg = g_rowptr[row];        end = g_rowptr[row + 1]; }
    else     { beg = g_rowptr_i[row - NU]; end = g_rowptr_i[row - NU + 1]; }
    const float4* sp = (const float4*)srcTab;   // 16 x float4 per row

    float4 a = make_float4(0.f, 0.f, 0.f, 0.f);
    int j = beg;
    for (; j + 4 <= end; j += 4) {
        int c0, c1, c2, c3;
        float v0, v1, v2, v3;
        if (RAW) {
            c0 = __ldg(&cols[j])     - NU; v0 = __ldg(&vals[j]);
            c1 = __ldg(&cols[j + 1]) - NU; v1 = __ldg(&vals[j + 1]);
            c2 = __ldg(&cols[j + 2]) - NU; v2 = __ldg(&vals[j + 2]);
            c3 = __ldg(&cols[j + 3]) - NU; v3 = __ldg(&vals[j + 3]);
        } else {
            unsigned long long pk0 = __ldg(&g_edges[j]);
            unsigned long long pk1 = __ldg(&g_edges[j + 1]);
            unsigned long long pk2 = __ldg(&g_edges[j + 2]);
            unsigned long long pk3 = __ldg(&g_edges[j + 3]);
            c0 = (int)(unsigned int)pk0; v0 = __uint_as_float((unsigned int)(pk0 >> 32));
            c1 = (int)(unsigned int)pk1; v1 = __uint_as_float((unsigned int)(pk1 >> 32));
            c2 = (int)(unsigned int)pk2; v2 = __uint_as_float((unsigned int)(pk2 >> 32));
            c3 = (int)(unsigned int)pk3; v3 = __uint_as_float((unsigned int)(pk3 >> 32));
        }
        float4 x0 = __ldg(sp + c0 * 16 + l);
        float4 x1 = __ldg(sp + c1 * 16 + l);
        float4 x2 = __ldg(sp + c2 * 16 + l);
        float4 x3 = __ldg(sp + c3 * 16 + l);
        a.x += v0 * x0.x; a.y += v0 * x0.y; a.z += v0 * x0.z; a.w += v0 * x0.w;
        a.x += v1 * x1.x; a.y += v1 * x1.y; a.z += v1 * x1.z; a.w += v1 * x1.w;
        a.x += v2 * x2.x; a.y += v2 * x2.y; a.z += v2 * x2.z; a.w += v2 * x2.w;
        a.x += v3 * x3.x; a.y += v3 * x3.y; a.z += v3 * x3.z; a.w += v3 * x3.w;
    }
    for (; j < end; j++) {
        int c; float v;
        if (RAW) { c = __ldg(&cols[j]) - NU; v = __ldg(&vals[j]); }
        else {
            unsigned long long pk = __ldg(&g_edges[j]);
            c = (int)(unsigned int)pk; v = __uint_as_float((unsigned int)(pk >> 32));
        }
        float4 x = __ldg(sp + c * 16 + l);
        a.x += v * x.x; a.y += v * x.y; a.z += v * x.z; a.w += v * x.w;
    }

    half2 o[2];
    o[0] = __floats2half2_rn(a.x, a.y);
    o[1] = __floats2half2_rn(a.z, a.w);
    ((uint2*)dst)[row * 16 + l] = *(uint2*)o;
}

// LAYER-2 SpMM: fp16 g_a gather (R6-proven 8 lanes/row, 16B per lane).
template <bool RAW>
__global__ void spmm_l2_kernel(const __half* __restrict__ src,
                               __half* __restrict__ dst,
                               int rowBeg, int rowEnd,
                               const int* __restrict__ cols,
                               const float* __restrict__ vals) {
    int gid = blockIdx.x * blockDim.x + threadIdx.x;
    int row = rowBeg + (gid >> 3);
    int l = gid & 7;
    if (row >= rowEnd) return;
    int beg, end;
    if (RAW) { beg = g_rowptr[row];        end = g_rowptr[row + 1]; }
    else     { beg = g_rowptr_i[row - NU]; end = g_rowptr_i[row - NU + 1]; }
    const uint4* sp = (const uint4*)src;

    float s0 = 0.f, s1 = 0.f, s2 = 0.f, s3 = 0.f,
          s4 = 0.f, s5 = 0.f, s6 = 0.f, s7 = 0.f;

#define ACCV(V, X) {                                                     \
        half2* h = (half2*)&(X);                                         \
        float2 f0 = __half22float2(h[0]);                                \
        float2 f1 = __half22float2(h[1]);                                \
        float2 f2 = __half22float2(h[2]);                                \
        float2 f3 = __half22float2(h[3]);                                \
        s0 += (V) * f0.x; s1 += (V) * f0.y; s2 += (V) * f1.x; s3 += (V) * f1.y; \
        s4 += (V) * f2.x; s5 += (V) * f2.y; s6 += (V) * f3.x; s7 += (V) * f3.y; }

    int j = beg;
    for (; j + 4 <= end; j += 4) {
        int c0, c1, c2, c3;
        float v0, v1, v2, v3;
        if (RAW) {
            c0 = __ldg(&cols[j]);     v0 = __ldg(&vals[j]);
            c1 = __ldg(&cols[j + 1]); v1 = __ldg(&vals[j + 1]);
            c2 = __ldg(&cols[j + 2]); v2 = __ldg(&vals[j + 2]);
            c3 = __ldg(&cols[j + 3]); v3 = __ldg(&vals[j + 3]);
        } else {
            unsigned long long pk0 = __ldg(&g_edges[j]);
            unsigned long long pk1 = __ldg(&g_edges[j + 1]);
            unsigned long long pk2 = __ldg(&g_edges[j + 2]);
            unsigned long long pk3 = __ldg(&g_edges[j + 3]);
            c0 = (int)(unsigned int)pk0; v0 = __uint_as_float((unsigned int)(pk0 >> 32));
            c1 = (int)(unsigned int)pk1; v1 = __uint_as_float((unsigned int)(pk1 >> 32));
            c2 = (int)(unsigned int)pk2; v2 = __uint_as_float((unsigned int)(pk2 >> 32));
            c3 = (int)(unsigned int)pk3; v3 = __uint_as_float((unsigned int)(pk3 >> 32));
        }
        uint4 x0 = __ldg(sp + c0 * 8 + l);
        uint4 x1 = __ldg(sp + c1 * 8 + l);
        uint4 x2 = __ldg(sp + c2 * 8 + l);
        uint4 x3 = __ldg(sp + c3 * 8 + l);
        ACCV(v0, x0) ACCV(v1, x1) ACCV(v2, x2) ACCV(v3, x3)
    }
    for (; j < end; j++) {
        int c; float v;
        if (RAW) { c = __ldg(&cols[j]); v = __ldg(&vals[j]); }
        else {
            unsigned long long pk = __ldg(&g_edges[j]);
            c = (int)(unsigned int)pk; v = __uint_as_float((unsigned int)(pk >> 32));
        }
        uint4 x = __ldg(sp + c * 8 + l);
        ACCV(v, x)
    }
#undef ACCV

    half2 o[4];
    o[0] = __floats2half2_rn(s0, s1);
    o[1] = __floats2half2_rn(s2, s3);
    o[2] = __floats2half2_rn(s4, s5);
    o[3] = __floats2half2_rn(s6, s7);
    ((uint4*)dst)[row * 8 + l] = *(uint4*)o;
}

// ---------------------------------------------------------------------------
// l3 gathers over g_b (fp16 half2 per lane).
__device__ __forceinline__ void l3_gather_pk(int beg, int end, int lane,
                                             float& ax, float& ay) {
    const unsigned* sp = (const unsigned*)g_b;
    int j = beg;
    for (; j + 4 <= end; j += 4) {
        unsigned long long pk0 = __ldg(&g_edges[j]);
        unsigned long long pk1 = __ldg(&g_edges[j + 1]);
        unsigned long long pk2 = __ldg(&g_edges[j + 2]);
        unsigned long long pk3 = __ldg(&g_edges[j + 3]);
        unsigned x0 = __ldg(sp + (int)(unsigned int)pk0 * 32 + lane);
        unsigned x1 = __ldg(sp + (int)(unsigned int)pk1 * 32 + lane);
        unsigned x2 = __ldg(sp + (int)(unsigned int)pk2 * 32 + lane);
        unsigned x3 = __ldg(sp + (int)(unsigned int)pk3 * 32 + lane);
        float v0 = __uint_as_float((unsigned int)(pk0 >> 32));
        float v1 = __uint_as_float((unsigned int)(pk1 >> 32));
        float v2 = __uint_as_float((unsigned int)(pk2 >> 32));
        float v3 = __uint_as_float((unsigned int)(pk3 >> 32));
        float2 f0 = __half22float2(*(half2*)&x0);
        float2 f1 = __half22float2(*(half2*)&x1);
        float2 f2 = __half22float2(*(half2*)&x2);
        float2 f3 = __half22float2(*(half2*)&x3);
        ax += v0 * f0.x; ay += v0 * f0.y;
        ax += v1 * f1.x; ay += v1 * f1.y;
        ax += v2 * f2.x; ay += v2 * f2.y;
        ax += v3 * f3.x; ay += v3 * f3.y;
    }
    for (; j < end; j++) {
        unsigned long long pk = __ldg(&g_edges[j]);
        unsigned x = __ldg(sp + (int)(unsigned int)pk * 32 + lane);
        float v = __uint_as_float((unsigned int)(pk >> 32));
        float2 f = __half22float2(*(half2*)&x);
        ax += v * f.x; ay += v * f.y;
    }
}

__device__ __forceinline__ void l3_gather_raw(int beg, int end, int lane,
                                              const int* __restrict__ cols,
                                              const float* __restrict__ vals,
                                              float& ax, float& ay) {
    const unsigned* sp = (const unsigned*)g_b;
    int j = beg;
    for (; j + 4 <= end; j += 4) {
        int c0 = __ldg(&cols[j]);     float v0 = __ldg(&vals[j]);
        int c1 = __ldg(&cols[j + 1]); float v1 = __ldg(&vals[j + 1]);
        int c2 = __ldg(&cols[j + 2]); float v2 = __ldg(&vals[j + 2]);
        int c3 = __ldg(&cols[j + 3]); float v3 = __ldg(&vals[j + 3]);
        unsigned x0 = __ldg(sp + c0 * 32 + lane);
        unsigned x1 = __ldg(sp + c1 * 32 + lane);
        unsigned x2 = __ldg(sp + c2 * 32 + lane);
        unsigned x3 = __ldg(sp + c3 * 32 + lane);
        float2 f0 = __half22float2(*(half2*)&x0);
        float2 f1 = __half22float2(*(half2*)&x1);
        float2 f2 = __half22float2(*(half2*)&x2);
        float2 f3 = __half22float2(*(half2*)&x3);
        ax += v0 * f0.x; ay += v0 * f0.y;
        ax += v1 * f1.x; ay += v1 * f1.y;
        ax += v2 * f2.x; ay += v2 * f2.y;
        ax += v3 * f3.x; ay += v3 * f3.y;
    }
    for (; j < end; j++) {
        int c = __ldg(&cols[j]); float v = __ldg(&vals[j]);
        unsigned x = __ldg(sp + c * 32 + lane);
        float2 f = __half22float2(*(half2*)&x);
        ax += v * f.x; ay += v * f.y;
    }
}

// USER-node partial (runs on SIDE, overlapped with main's L2_user):
// au_partial = e0[u] + l1[u] + l3(u over g_b item cols). Missing g_b[u] term
// (produced by L2_user) is added in final_join. One warp per batch element.
__global__ void final_user_partial(const float* __restrict__ eu0,
                                   const int* __restrict__ cols,
                                   const float* __restrict__ vals,
                                   const int* __restrict__ user, int B) {
    int w = (int)((blockIdx.x * (long long)blockDim.x + threadIdx.x) >> 5);
    int lane = threadIdx.x & 31;
    if (w >= B) return;
    int u = __ldg(&user[w]);
    float2 v0 = __ldg((const float2*)eu0 + u * 32 + lane);
    float ax = v0.x, ay = v0.y;
    float sq = v0.x * v0.x + v0.y * v0.y;
    float2 t = __half22float2(((const half2*)g_a)[u * 32 + lane]);
    ax += t.x; ay += t.y;
    l3_gather_raw(g_rowptr[u], g_rowptr[u + 1], lane, cols, vals, ax, ay);
    g_s[w * D + 2 * lane] = ax;
    g_s[w * D + 2 * lane + 1] = ay;
#pragma unroll
    for (int o = 16; o; o >>= 1) sq += __shfl_xor_sync(0xFFFFFFFFu, sq, o);
    if (lane == 0) g_sreg[w] = sq;
}

// JOIN (main, after everything): item-node accums + add g_b[u] + dots.
__global__ void final_join(const float* __restrict__ ei0,
                           const int* __restrict__ user,
                           const int* __restrict__ item_i,
                           const int* __restrict__ item_j,
                           float* __restrict__ out, int B) {
    __shared__ float sm[3][64];
    __shared__ float regp[2];
    int bidx = blockIdx.x;
    int w = threadIdx.x >> 5;
    int lane = threadIdx.x & 31;
    if (bidx >= B) return;

    if (w == 0) {
        int u = __ldg(&user[bidx]);
        float ax = g_s[bidx * D + 2 * lane];
        float ay = g_s[bidx * D + 2 * lane + 1];
        float2 t = __half22float2(((const half2*)g_b)[u * 32 + lane]);
        ax += t.x; ay += t.y;
        sm[0][2 * lane] = ax;
        sm[0][2 * lane + 1] = ay;
    } else {
        int it = (w == 1) ? __ldg(&item_i[bidx]) : __ldg(&item_j[bidx]);
        int n = NU + it;
        float2 v0 = __ldg((const float2*)ei0 + it * 32 + lane);
        float ax = v0.x, ay = v0.y;
        float sq = v0.x * v0.x + v0.y * v0.y;
        float2 t;
        t = __half22float2(((const half2*)g_a)[n * 32 + lane]); ax += t.x; ay += t.y;
        t = __half22float2(((const half2*)g_b)[n * 32 + lane]); ax += t.x; ay += t.y;
        l3_gather_pk(g_rowptr_i[it], g_rowptr_i[it + 1], lane, ax, ay);
        sm[w][2 * lane] = ax;
        sm[w][2 * lane + 1] = ay;
#pragma unroll
        for (int o = 16; o; o >>= 1) sq += __shfl_xor_sync(0xFFFFFFFFu, sq, o);
        if (lane == 0) regp[w - 1] = sq;
    }
    __syncthreads();

    if (w == 0) {
        float p = sm[0][2 * lane] * sm[1][2 * lane]
                + sm[0][2 * lane + 1] * sm[1][2 * lane + 1];
#pragma unroll
        for (int o = 16; o; o >>= 1) p += __shfl_xor_sync(0xFFFFFFFFu, p, o);
        if (lane == 0) out[bidx] = p * (1.f / 16.f);
    } else if (w == 1) {
        float p = sm[0][2 * lane] * sm[2][2 * lane]
                + sm[0][2 * lane + 1] * sm[2][2 * lane + 1];
#pragma unroll
        for (int o = 16; o; o >>= 1) p += __shfl_xor_sync(0xFFFFFFFFu, p, o);
        if (lane == 0) out[B + bidx] = p * (1.f / 16.f);
    } else {
        if (lane == 0) {
            float reg = g_sreg[bidx] + regp[0] + regp[1];
            atomicAdd(out + 2 * B, reg * (0.5f / (float)B));
        }
    }
}

// ---------------------------------------------------------------------------
extern "C" void kernel_launch(void* const* d_in, const int* in_sizes, int n_in,
                              void* d_out, int out_size) {
    const float* eu0    = (const float*)d_in[0];
    const float* ei0    = (const float*)d_in[1];
    const int*   rows   = (const int*)d_in[2];
    const int*   cols   = (const int*)d_in[3];
    const float* vals   = (const float*)d_in[4];
    const int*   user   = (const int*)d_in[5];
    const int*   item_i = (const int*)d_in[6];
    const int*   item_j = (const int*)d_in[7];

    int E = in_sizes[2];
    int H = E / 2;          // first half: user rows (sorted); second: item rows
    int B = in_sizes[5];
    float* out = (float*)d_out;

    __half *pa, *pb;
    cudaGetSymbolAddress((void**)&pa, g_a);
    cudaGetSymbolAddress((void**)&pb, g_b);

    const int T = 256;
    int u1grid = (NU * 16 + T - 1) / T;  // L1 user (16 lanes/row)
    int i1grid = (MI * 16 + T - 1) / T;  // L1 item
    int u2grid = (NU * 8 + T - 1) / T;   // L2 user (8 lanes/row)
    int i2grid = (MI * 8 + T - 1) / T;   // L2 item
    int cgrid = (MI + T - 1) / T;
    int pgrid = (B * 32 + T - 1) / T;    // final_user_partial

    if (g_sr.ok) {
        cudaStream_t s = g_sr.side;
        cudaEventRecord(g_sr.eFork, 0);
        cudaStreamWaitEvent(s, g_sr.eFork, 0);

        // main: item CSR build chain
        hist_kernel<<<(H + T - 1) / T, T>>>(rows, H, out, B);
        cudaEventRecord(g_sr.eHist, 0);
        scan1_kernel<<<NBLK_I, 256>>>();
        scan2_kernel<<<NBLK_I, 256>>>(H);
        scatter_edges_kernel<<<(H + T - 1) / T, T>>>(rows, cols, vals, H);
        cudaEventRecord(g_sr.eScat, 0);

        // side: L1 user rows (fp32 gather from ei0; needs user rowptr [eHist])
        cudaStreamWaitEvent(s, g_sr.eHist, 0);
        spmm_l1_kernel<true><<<u1grid, T, 0, s>>>(ei0, pa, 0, NU, cols, vals);
        // side: L2 item rows (g_a USER cols = L1_user same-stream; item CSR [eScat])
        cudaStreamWaitEvent(s, g_sr.eScat, 0);
        spmm_l2_kernel<false><<<i2grid, T, 0, s>>>(pa, pb, NU, NN, cols, vals);
        // side: user-node final partial (L1_user + L2_item same-stream)
        final_user_partial<<<pgrid, T, 0, s>>>(eu0, cols, vals, user, B);
        // side: tail clear
        clear_kernel<<<cgrid, T, 0, s>>>();
        cudaEventRecord(g_sr.eSide, s);

        // main: L1 item rows (fp32 gather from eu0; scatter same-stream)
        spmm_l1_kernel<false><<<i1grid, T>>>(eu0, pa, NU, NN, cols, vals);
        // main: L2 user rows (g_a ITEM cols = L1_item same-stream)
        spmm_l2_kernel<true><<<u2grid, T>>>(pa, pb, 0, NU, cols, vals);

        // join side, then item-node accums + dots
        cudaStreamWaitEvent(0, g_sr.eSide, 0);
        final_join<<<B, 96>>>(ei0, user, item_i, item_j, out, B);
    } else {
        // serial fallback (single stream)
        hist_kernel<<<(H + T - 1) / T, T>>>(rows, H, out, B);
        scan1_kernel<<<NBLK_I, 256>>>();
        scan2_kernel<<<NBLK_I, 256>>>(H);
        scatter_edges_kernel<<<(H + T - 1) / T, T>>>(rows, cols, vals, H);
        spmm_l1_kernel<true ><<<u1grid, T>>>(ei0, pa, 0, NU, cols, vals);
        spmm_l1_kernel<false><<<i1grid, T>>>(eu0, pa, NU, NN, cols, vals);
        spmm_l2_kernel<false><<<i2grid, T>>>(pa, pb, NU, NN, cols, vals);
        spmm_l2_kernel<true ><<<u2grid, T>>>(pa, pb, 0, NU, cols, vals);
        final_user_partial<<<pgrid, T>>>(eu0, cols, vals, user, B);
        clear_kernel<<<cgrid, T>>>();
        final_join<<<B, 96>>>(ei0, user, item_i, item_j, out, B);
    }
}